// round 3
// baseline (speedup 1.0000x reference)
#include <cuda_runtime.h>
#include <cstdint>

// ---------------------------------------------------------------------------
// Problem constants
// ---------------------------------------------------------------------------
#define GG      8          // number of groups (record_len.shape[0])
#define LL      4096       // sequence length = H*W
#define CC      256        // model dim
#define NST     8          // d_state
#define RNK     16         // dt_rank
#define DEPTHN  4
#define NROWS   (GG*LL)    // 32768 "token rows"
#define LCH     64         // scan chunk length
#define NCH     (LL/LCH)   // 64 chunks

// ---------------------------------------------------------------------------
// Scratch (device globals; no runtime allocation allowed). Referenced directly
// from device code — kernel_launch performs NO runtime API calls besides
// kernel launches (graph-capture safe by construction).
// ---------------------------------------------------------------------------
__device__ float g_x    [NROWS*CC];        // current activations (g,l,c)
__device__ float g_xn   [NROWS*CC];        // layernorm out / out_proj out
__device__ float g_xz   [NROWS*2*CC];      // in_proj output (xx | z)
__device__ float g_xc   [2*NROWS*CC];      // conv+silu per direction
__device__ float g_xdbl [2*NROWS*32];      // x_proj output (dt|B|C)
__device__ float g_delta[2*NROWS*CC];      // softplus(dt_proj)
__device__ float g_ydir [2*NROWS*CC];      // scan output per direction
__device__ float g_hloc [2*GG*NCH*CC*NST]; // chunk-local final states
__device__ float g_hini [2*GG*NCH*CC*NST]; // chunk initial states
__device__ float g_S    [2*GG*NCH*CC];     // per-chunk delta sums

// ---------------------------------------------------------------------------
// 0) segment mean + transpose: data (B,C,HW) -> g_x (g, l, c)
// ---------------------------------------------------------------------------
__global__ void mean_kernel(const float* __restrict__ data,
                            const int* __restrict__ rl) {
    __shared__ float tile[32][33];
    int g  = blockIdx.z;
    int c0 = blockIdx.y * 32;
    int l0 = blockIdx.x * 32;
    int off = 0;
    for (int i = 0; i < g; i++) off += rl[i];
    int cnt = rl[g];
    float inv = 1.0f / (float)cnt;
    // read coalesced along l
    for (int cc = threadIdx.y; cc < 32; cc += 8) {
        int c = c0 + cc;
        int l = l0 + threadIdx.x;
        float s = 0.f;
        for (int a = 0; a < cnt; a++)
            s += data[((size_t)(off + a) * CC + c) * LL + l];
        tile[cc][threadIdx.x] = s * inv;
    }
    __syncthreads();
    // write coalesced along c
    for (int lc = threadIdx.y; lc < 32; lc += 8) {
        int l = l0 + lc;
        int c = c0 + threadIdx.x;
        g_x[((size_t)g * LL + l) * CC + c] = tile[threadIdx.x][lc];
    }
}

// ---------------------------------------------------------------------------
// final transpose: g_x (g,l,c) -> out (g,c,l)
// ---------------------------------------------------------------------------
__global__ void out_transpose(float* __restrict__ out) {
    __shared__ float tile[32][33];
    int g  = blockIdx.z;
    int c0 = blockIdx.y * 32;
    int l0 = blockIdx.x * 32;
    for (int lc = threadIdx.y; lc < 32; lc += 8)
        tile[threadIdx.x][lc] = g_x[((size_t)g * LL + l0 + lc) * CC + c0 + threadIdx.x];
    __syncthreads();
    for (int cc = threadIdx.y; cc < 32; cc += 8)
        out[((size_t)g * CC + c0 + cc) * LL + l0 + threadIdx.x] = tile[cc][threadIdx.x];
}

// ---------------------------------------------------------------------------
// LayerNorm over C=256 (1 warp per row, 8 elems/lane).
// MODE 0: out = LN(g_x)                 -> g_xn     (pre-norm)
// MODE 1: g_x = LN(g_xn) + g_x          (post-norm + residual, in place)
// ---------------------------------------------------------------------------
template<int MODE>
__global__ void ln_kernel(const float* __restrict__ w,
                          const float* __restrict__ b) {
    int row  = blockIdx.x * 8 + (threadIdx.x >> 5);
    int lane = threadIdx.x & 31;
    const float* r = (MODE == 0 ? g_x : g_xn) + (size_t)row * CC;
    float v[8];
    float s = 0.f, s2 = 0.f;
#pragma unroll
    for (int k = 0; k < 8; k++) {
        v[k] = r[k * 32 + lane];
        s  += v[k];
        s2 += v[k] * v[k];
    }
#pragma unroll
    for (int o = 16; o; o >>= 1) {
        s  += __shfl_xor_sync(0xffffffffu, s,  o);
        s2 += __shfl_xor_sync(0xffffffffu, s2, o);
    }
    float mu  = s * (1.0f / CC);
    float var = s2 * (1.0f / CC) - mu * mu;
    float inv = rsqrtf(var + 1e-5f);
    float* o_ = (MODE == 0 ? g_xn : g_x) + (size_t)row * CC;
#pragma unroll
    for (int k = 0; k < 8; k++) {
        int cc = k * 32 + lane;
        float y = (v[k] - mu) * inv * w[cc] + b[cc];
        if (MODE == 1) y += g_x[(size_t)row * CC + cc];
        o_[cc] = y;
    }
}

// ---------------------------------------------------------------------------
// Tiled fp32 GEMM: Cout[m,n] = sum_k A[m,k] * W[n,k], K = 256 always.
// MODE 0: in_proj   A=g_xn,  C=g_xz,   N=512
// MODE 1: x_proj    A=g_xc + z*NROWS*C, C=g_xdbl + z*NROWS*32, N=32 (gridDim.z=2)
// MODE 2: out_proj  A=0.5*(g_ydir fwd + bwd), C=g_xn, N=256
// ---------------------------------------------------------------------------
template<int MODE, int BM, int BN, int BK, int TM, int TN>
__global__ void gemm_kernel(const float* __restrict__ W) {
    const float* A;
    float* Cout;
    int Nn;
    const int Ka = CC;
    if (MODE == 0)      { A = g_xn;  Cout = g_xz;   Nn = 2 * CC; }
    else if (MODE == 1) { A = g_xc  + (size_t)blockIdx.z * NROWS * CC;
                          Cout = g_xdbl + (size_t)blockIdx.z * NROWS * 32; Nn = 32; }
    else                { A = g_ydir; Cout = g_xn;  Nn = CC; }

    __shared__ float As[BM][BK + 1];
    __shared__ float Bs[BN][BK + 1];
    int bm = blockIdx.y * BM;
    int bn = blockIdx.x * BN;
    const int tid = threadIdx.x;
    const int tx  = tid % (BN / TN);
    const int ty  = tid / (BN / TN);
    float acc[TM][TN];
#pragma unroll
    for (int i = 0; i < TM; i++)
#pragma unroll
        for (int j = 0; j < TN; j++) acc[i][j] = 0.f;

    for (int k0 = 0; k0 < Ka; k0 += BK) {
        for (int idx = tid; idx < BM * BK; idx += 256) {
            int m = idx / BK, k = idx % BK;
            float v = A[(size_t)(bm + m) * Ka + k0 + k];
            if (MODE == 2)
                v = 0.5f * (v + g_ydir[(size_t)NROWS * CC + (size_t)(bm + m) * Ka + k0 + k]);
            As[m][k] = v;
        }
        for (int idx = tid; idx < BN * BK; idx += 256) {
            int n = idx / BK, k = idx % BK;
            Bs[n][k] = W[(size_t)(bn + n) * Ka + k0 + k];
        }
        __syncthreads();
#pragma unroll
        for (int k = 0; k < BK; k++) {
            float a[TM], bb[TN];
#pragma unroll
            for (int i = 0; i < TM; i++) a[i]  = As[ty * TM + i][k];
#pragma unroll
            for (int j = 0; j < TN; j++) bb[j] = Bs[tx * TN + j][k];
#pragma unroll
            for (int i = 0; i < TM; i++)
#pragma unroll
                for (int j = 0; j < TN; j++)
                    acc[i][j] += a[i] * bb[j];
        }
        __syncthreads();
    }
#pragma unroll
    for (int i = 0; i < TM; i++)
#pragma unroll
        for (int j = 0; j < TN; j++)
            Cout[(size_t)(bm + ty * TM + i) * Nn + bn + tx * TN + j] = acc[i][j];
}

// ---------------------------------------------------------------------------
// Depthwise causal conv (k=4) + SiLU, both directions
//   fwd: taps at l-3..l ; bwd: taps at l..l+3 (weights reversed)
// xx lives inside g_xz with row stride 2C.
// ---------------------------------------------------------------------------
__global__ void conv_silu_kernel(const float* __restrict__ w,
                                 const float* __restrict__ b) {
    size_t i   = (size_t)blockIdx.x * 256 + threadIdx.x;   // over 2*NROWS*CC
    int d      = (int)(i & (CC - 1));
    size_t rg  = i >> 8;                                   // dir*NROWS + g*L + l
    int dir    = rg >= (size_t)NROWS;
    size_t row = rg - (size_t)dir * NROWS;                 // g*L + l
    int l = (int)(row & (LL - 1));
    int g = (int)(row >> 12);
    float acc = b[d];
#pragma unroll
    for (int k = 0; k < 4; k++) {
        int ls = (dir == 0) ? (l - 3 + k) : (l + 3 - k);
        if (ls >= 0 && ls < LL)
            acc += w[d * 4 + k] * g_xz[((size_t)g * LL + ls) * (2 * CC) + d];
    }
    float sv = acc / (1.0f + __expf(-acc));
    g_xc[(size_t)dir * NROWS * CC + row * CC + d] = sv;
}

// ---------------------------------------------------------------------------
// dt_proj (K=16) + softplus, both directions. One block per row.
// ---------------------------------------------------------------------------
__global__ void dtproj_kernel(const float* __restrict__ dtw,
                              const float* __restrict__ dtb) {
    int row = blockIdx.x;
    int dir = blockIdx.y;
    const float* xr = g_xdbl + (size_t)dir * NROWS * 32 + (size_t)row * 32;
    float dt[RNK];
#pragma unroll
    for (int r = 0; r < RNK; r++) dt[r] = __ldg(xr + r);
    int d = threadIdx.x;
    float v = dtb[d];
#pragma unroll
    for (int r = 0; r < RNK; r++) v += dtw[d * RNK + r] * dt[r];
    v = (v > 20.f) ? v : log1pf(__expf(v));
    g_delta[(size_t)dir * NROWS * CC + (size_t)row * CC + d] = v;
}

// ---------------------------------------------------------------------------
// Selective scan, chunked (3 phases).
// Per (g,d,n):  h <- exp(delta*A[d,n])*h + delta*u*B[g,t,n]
// Chunk decay exp(A * sum delta) is exact -> exact chunk combine.
// Backward direction iterates original index l = L-1 - tau.
// ---------------------------------------------------------------------------
__global__ void scan_phase1(const float* __restrict__ Alog_f,
                            const float* __restrict__ Alog_b) {
    int c = blockIdx.x, g = blockIdx.y, dir = blockIdx.z;
    int d = threadIdx.x;
    const float* Alog = dir ? Alog_b : Alog_f;
    float A[NST];
#pragma unroll
    for (int n = 0; n < NST; n++) A[n] = -__expf(Alog[d * NST + n]);

    const float* del = g_delta + (size_t)dir * NROWS * CC;
    const float* uu_ = g_xc    + (size_t)dir * NROWS * CC;
    const float* xd  = g_xdbl  + (size_t)dir * NROWS * 32;

    float h[NST];
#pragma unroll
    for (int n = 0; n < NST; n++) h[n] = 0.f;
    float S = 0.f;

    for (int t = 0; t < LCH; t++) {
        int tau = c * LCH + t;
        int l   = (dir == 0) ? tau : (LL - 1 - tau);
        size_t row = (size_t)g * LL + l;
        float dl = del[row * CC + d];
        float uv = uu_[row * CC + d];
        S += dl;
        float du = dl * uv;
#pragma unroll
        for (int n = 0; n < NST; n++) {
            float Bn = __ldg(xd + row * 32 + 16 + n);
            h[n] = __expf(dl * A[n]) * h[n] + du * Bn;
        }
    }
    size_t base = ((size_t)dir * GG * NCH + (size_t)g * NCH + c) * CC + d;
#pragma unroll
    for (int n = 0; n < NST; n++) g_hloc[base * NST + n] = h[n];
    g_S[base] = S;
}

__global__ void scan_phase2(const float* __restrict__ Alog_f,
                            const float* __restrict__ Alog_b) {
    int t = blockIdx.x * 256 + threadIdx.x;   // 2*G*C*NST = 32768
    int n   = t & 7;
    int d   = (t >> 3) & 255;
    int g   = (t >> 11) & 7;
    int dir = t >> 14;
    const float* Alog = dir ? Alog_b : Alog_f;
    float A = -__expf(Alog[d * NST + n]);
    float h = 0.f;
    for (int c = 0; c < NCH; c++) {
        size_t base = ((size_t)dir * GG * NCH + (size_t)g * NCH + c) * CC + d;
        g_hini[base * NST + n] = h;
        float S = g_S[base];
        h = __expf(A * S) * h + g_hloc[base * NST + n];
    }
}

__global__ void scan_phase3(const float* __restrict__ Alog_f,
                            const float* __restrict__ Alog_b,
                            const float* __restrict__ Dp) {
    int c = blockIdx.x, g = blockIdx.y, dir = blockIdx.z;
    int d = threadIdx.x;
    const float* Alog = dir ? Alog_b : Alog_f;
    float A[NST];
#pragma unroll
    for (int n = 0; n < NST; n++) A[n] = -__expf(Alog[d * NST + n]);
    float Dv = Dp[d];

    const float* del = g_delta + (size_t)dir * NROWS * CC;
    const float* uu_ = g_xc    + (size_t)dir * NROWS * CC;
    const float* xd  = g_xdbl  + (size_t)dir * NROWS * 32;
    float* yo        = g_ydir  + (size_t)dir * NROWS * CC;

    size_t base = ((size_t)dir * GG * NCH + (size_t)g * NCH + c) * CC + d;
    float h[NST];
#pragma unroll
    for (int n = 0; n < NST; n++) h[n] = g_hini[base * NST + n];

    for (int t = 0; t < LCH; t++) {
        int tau = c * LCH + t;
        int l   = (dir == 0) ? tau : (LL - 1 - tau);
        size_t row = (size_t)g * LL + l;
        float dl = del[row * CC + d];
        float uv = uu_[row * CC + d];
        float du = dl * uv;
        float y  = 0.f;
#pragma unroll
        for (int n = 0; n < NST; n++) {
            float Bn = __ldg(xd + row * 32 + 16 + n);
            float Cn = __ldg(xd + row * 32 + 24 + n);
            h[n] = __expf(dl * A[n]) * h[n] + du * Bn;
            y += h[n] * Cn;
        }
        float z  = g_xz[row * (2 * CC) + CC + d];
        float sz = z / (1.0f + __expf(-z));
        yo[row * CC + d] = (y + Dv * uv) * sz;
    }
}

// ---------------------------------------------------------------------------
// Host launcher — kernel launches only, no other runtime API calls.
// ---------------------------------------------------------------------------
extern "C" void kernel_launch(void* const* d_in, const int* in_sizes, int n_in,
                              void* d_out, int out_size) {
    const float* data  = (const float*)d_in[0];
    const float* ln_w  = (const float*)d_in[1];
    const float* ln_b  = (const float*)d_in[2];
    const float* inpw  = (const float*)d_in[3];
    const float* convw = (const float*)d_in[4];
    const float* convb = (const float*)d_in[5];
    const float* xprw  = (const float*)d_in[6];
    const float* dtw   = (const float*)d_in[7];
    const float* dtb   = (const float*)d_in[8];
    const float* Alog  = (const float*)d_in[9];
    const float* Ablog = (const float*)d_in[10];
    const float* Dmat  = (const float*)d_in[11];
    const float* outw  = (const float*)d_in[12];
    const float* mn_w  = (const float*)d_in[13];
    const float* mn_b  = (const float*)d_in[14];
    const int*   rl    = (const int*)  d_in[15];

    dim3 tposeGrid(LL / 32, CC / 32, GG);
    dim3 tposeBlk(32, 8);

    mean_kernel<<<tposeGrid, tposeBlk>>>(data, rl);

    for (int i = 0; i < DEPTHN; i++) {
        const float* lnw_i  = ln_w  + i * CC;
        const float* lnb_i  = ln_b  + i * CC;
        const float* inw_i  = inpw  + (size_t)i * 2 * CC * CC;
        const float* cw_i   = convw + i * CC * 4;
        const float* cb_i   = convb + i * CC;
        const float* xpw_i  = xprw  + (size_t)i * 32 * CC;
        const float* dtw_i  = dtw   + (size_t)i * CC * RNK;
        const float* dtb_i  = dtb   + i * CC;
        const float* Al_i   = Alog  + (size_t)i * CC * NST;
        const float* Ab_i   = Ablog + (size_t)i * CC * NST;
        const float* D_i    = Dmat  + i * CC;
        const float* ow_i   = outw  + (size_t)i * CC * CC;
        const float* mnw_i  = mn_w  + i * CC;
        const float* mnb_i  = mn_b  + i * CC;

        // 1. pre-LayerNorm:          g_x -> g_xn
        ln_kernel<0><<<NROWS / 8, 256>>>(lnw_i, lnb_i);
        // 2. in_proj (32768x256)x(512x256)^T -> g_xz
        gemm_kernel<0, 128, 64, 16, 8, 4>
            <<<dim3(512 / 64, NROWS / 128), 256>>>(inw_i);
        // 3. causal conv + silu, both directions -> g_xc
        conv_silu_kernel<<<(2 * NROWS * CC) / 256, 256>>>(cw_i, cb_i);
        // 4. x_proj both directions (gridDim.z = 2) -> g_xdbl
        gemm_kernel<1, 128, 32, 16, 8, 2>
            <<<dim3(1, NROWS / 128, 2), 256>>>(xpw_i);
        // 5. dt_proj + softplus -> g_delta
        dtproj_kernel<<<dim3(NROWS, 2), 256>>>(dtw_i, dtb_i);
        // 6. chunked selective scan -> g_ydir
        scan_phase1<<<dim3(NCH, GG, 2), 256>>>(Al_i, Ab_i);
        scan_phase2<<<(2 * GG * CC * NST) / 256, 256>>>(Al_i, Ab_i);
        scan_phase3<<<dim3(NCH, GG, 2), 256>>>(Al_i, Ab_i, D_i);
        // 7. out_proj with A = 0.5*(y_f + y_b) -> g_xn
        gemm_kernel<2, 128, 64, 16, 8, 4>
            <<<dim3(256 / 64, NROWS / 128), 256>>>(ow_i);
        // 8. post-norm + residual (in-place update of g_x)
        ln_kernel<1><<<NROWS / 8, 256>>>(mnw_i, mnb_i);
    }

    out_transpose<<<tposeGrid, tposeBlk>>>((float*)d_out);
}

// round 4
// speedup vs baseline: 1.3712x; 1.3712x over previous
#include <cuda_runtime.h>
#include <cstdint>

// ---------------------------------------------------------------------------
// Problem constants
// ---------------------------------------------------------------------------
#define GG      8          // number of groups (record_len.shape[0])
#define LL      4096       // sequence length = H*W
#define CC      256        // model dim
#define NST     8          // d_state
#define RNK     16         // dt_rank
#define DEPTHN  4
#define NROWS   (GG*LL)    // 32768 "token rows"
#define LCH     64         // scan chunk length
#define NCH     (LL/LCH)   // 64 chunks

// ---------------------------------------------------------------------------
// Scratch (device globals; no runtime allocation allowed)
// ---------------------------------------------------------------------------
__device__ float g_x    [NROWS*CC];        // current activations (g,l,c)
__device__ float g_xn   [NROWS*CC];        // layernorm out / out_proj out
__device__ float g_xz   [NROWS*2*CC];      // in_proj output (xx | z)
__device__ float g_xc   [2*NROWS*CC];      // conv+silu per direction
__device__ float g_xdbl [2*NROWS*32];      // x_proj output (dt|B|C)
__device__ float g_delta[2*NROWS*CC];      // softplus(dt_proj)
__device__ float g_ydir [2*NROWS*CC];      // scan output per direction
__device__ float g_hloc [2*GG*NCH*CC*NST]; // chunk-local final states
__device__ float g_hini [2*GG*NCH*CC*NST]; // chunk initial states
__device__ float g_S    [2*GG*NCH*CC];     // per-chunk delta sums

// ---------------------------------------------------------------------------
// 0) segment mean + transpose: data (B,C,HW) -> g_x (g, l, c)
// ---------------------------------------------------------------------------
__global__ void mean_kernel(const float* __restrict__ data,
                            const int* __restrict__ rl) {
    __shared__ float tile[32][33];
    int g  = blockIdx.z;
    int c0 = blockIdx.y * 32;
    int l0 = blockIdx.x * 32;
    int off = 0;
    for (int i = 0; i < g; i++) off += rl[i];
    int cnt = rl[g];
    float inv = 1.0f / (float)cnt;
    for (int cc = threadIdx.y; cc < 32; cc += 8) {
        int c = c0 + cc;
        int l = l0 + threadIdx.x;
        float s = 0.f;
        for (int a = 0; a < cnt; a++)
            s += data[((size_t)(off + a) * CC + c) * LL + l];
        tile[cc][threadIdx.x] = s * inv;
    }
    __syncthreads();
    for (int lc = threadIdx.y; lc < 32; lc += 8) {
        int l = l0 + lc;
        int c = c0 + threadIdx.x;
        g_x[((size_t)g * LL + l) * CC + c] = tile[threadIdx.x][lc];
    }
}

// ---------------------------------------------------------------------------
// final transpose: g_x (g,l,c) -> out (g,c,l)
// ---------------------------------------------------------------------------
__global__ void out_transpose(float* __restrict__ out) {
    __shared__ float tile[32][33];
    int g  = blockIdx.z;
    int c0 = blockIdx.y * 32;
    int l0 = blockIdx.x * 32;
    for (int lc = threadIdx.y; lc < 32; lc += 8)
        tile[threadIdx.x][lc] = g_x[((size_t)g * LL + l0 + lc) * CC + c0 + threadIdx.x];
    __syncthreads();
    for (int cc = threadIdx.y; cc < 32; cc += 8)
        out[((size_t)g * CC + c0 + cc) * LL + l0 + threadIdx.x] = tile[cc][threadIdx.x];
}

// ---------------------------------------------------------------------------
// LayerNorm over C=256 (1 warp per row, 8 elems/lane).
// MODE 0: g_xn = LN(g_x)        MODE 1: g_x = LN(g_xn) + g_x
// ---------------------------------------------------------------------------
template<int MODE>
__global__ void ln_kernel(const float* __restrict__ w,
                          const float* __restrict__ b) {
    int row  = blockIdx.x * 8 + (threadIdx.x >> 5);
    int lane = threadIdx.x & 31;
    const float* r = (MODE == 0 ? g_x : g_xn) + (size_t)row * CC;
    float v[8];
    float s = 0.f, s2 = 0.f;
#pragma unroll
    for (int k = 0; k < 8; k++) {
        v[k] = r[k * 32 + lane];
        s  += v[k];
        s2 += v[k] * v[k];
    }
#pragma unroll
    for (int o = 16; o; o >>= 1) {
        s  += __shfl_xor_sync(0xffffffffu, s,  o);
        s2 += __shfl_xor_sync(0xffffffffu, s2, o);
    }
    float mu  = s * (1.0f / CC);
    float var = s2 * (1.0f / CC) - mu * mu;
    float inv = rsqrtf(var + 1e-5f);
    float* o_ = (MODE == 0 ? g_xn : g_x) + (size_t)row * CC;
#pragma unroll
    for (int k = 0; k < 8; k++) {
        int cc = k * 32 + lane;
        float y = (v[k] - mu) * inv * w[cc] + b[cc];
        if (MODE == 1) y += g_x[(size_t)row * CC + cc];
        o_[cc] = y;
    }
}

// ---------------------------------------------------------------------------
// Tensor-core tf32 GEMM:  Cout[m,n] = sum_k A[m,k] * W[n,k]   (K = 256)
// via mma.sync.aligned.m16n8k8.row.col.f32.tf32.tf32.f32
// MODE 0: in_proj   A=g_xn,   C=g_xz,   N=512
// MODE 1: x_proj    A=g_xc  + z*NROWS*CC, C=g_xdbl + z*NROWS*32, N=32
// MODE 2: out_proj  A=0.5*(g_ydir fwd + bwd), C=g_xn, N=256
// ---------------------------------------------------------------------------
__device__ __forceinline__ unsigned f2tf(float x) {
    unsigned r;
    asm("cvt.rna.tf32.f32 %0, %1;" : "=r"(r) : "f"(x));
    return r;
}

template<int MODE, int BM, int BN, int WARPS_M, int WARPS_N>
__global__ void tc_gemm(const float* __restrict__ W) {
    constexpr int BK  = 32;
    constexpr int SW  = BK + 4;              // smem word stride (conflict-free)
    constexpr int WM  = BM / WARPS_M;
    constexpr int WN  = BN / WARPS_N;
    constexpr int MT  = WM / 16;             // m16 tiles per warp
    constexpr int NT  = WN / 8;              // n8 tiles per warp

    const float* A;
    float* Cout;
    int Nn;
    if (MODE == 0)      { A = g_xn;  Cout = g_xz;   Nn = 2 * CC; }
    else if (MODE == 1) { A = g_xc  + (size_t)blockIdx.z * NROWS * CC;
                          Cout = g_xdbl + (size_t)blockIdx.z * NROWS * 32; Nn = 32; }
    else                { A = g_ydir; Cout = g_xn;  Nn = CC; }

    __shared__ __align__(16) unsigned As[BM * SW];
    __shared__ __align__(16) unsigned Bs[BN * SW];

    const int bm   = blockIdx.y * BM;
    const int bn   = blockIdx.x * BN;
    const int tid  = threadIdx.x;
    const int lane = tid & 31;
    const int warp = tid >> 5;
    const int wm   = (warp / WARPS_N) * WM;
    const int wn   = (warp % WARPS_N) * WN;

    float c[MT][NT][4];
#pragma unroll
    for (int i = 0; i < MT; i++)
#pragma unroll
        for (int j = 0; j < NT; j++)
#pragma unroll
            for (int q = 0; q < 4; q++) c[i][j][q] = 0.f;

    for (int k0 = 0; k0 < CC; k0 += BK) {
        // ---- stage A tile (BM x 32) as tf32, float4 granularity ----
        for (int idx = tid; idx < BM * 8; idx += 256) {
            int m  = idx >> 3;
            int kq = idx & 7;
            const float4 v = *(const float4*)(A + (size_t)(bm + m) * CC + k0 + kq * 4);
            float4 u = v;
            if (MODE == 2) {
                const float4 w2 = *(const float4*)(g_ydir + (size_t)NROWS * CC +
                                                   (size_t)(bm + m) * CC + k0 + kq * 4);
                u.x = 0.5f * (u.x + w2.x); u.y = 0.5f * (u.y + w2.y);
                u.z = 0.5f * (u.z + w2.z); u.w = 0.5f * (u.w + w2.w);
            }
            uint4 t;
            t.x = f2tf(u.x); t.y = f2tf(u.y); t.z = f2tf(u.z); t.w = f2tf(u.w);
            *(uint4*)(As + m * SW + kq * 4) = t;
        }
        // ---- stage W tile (BN x 32) as tf32 ----
        for (int idx = tid; idx < BN * 8; idx += 256) {
            int n  = idx >> 3;
            int kq = idx & 7;
            const float4 v = *(const float4*)(W + (size_t)(bn + n) * CC + k0 + kq * 4);
            uint4 t;
            t.x = f2tf(v.x); t.y = f2tf(v.y); t.z = f2tf(v.z); t.w = f2tf(v.w);
            *(uint4*)(Bs + n * SW + kq * 4) = t;
        }
        __syncthreads();

#pragma unroll
        for (int ks = 0; ks < BK / 8; ks++) {
            const int kk = ks * 8 + (lane & 3);
            unsigned a[MT][4], bfr[NT][2];
#pragma unroll
            for (int i = 0; i < MT; i++) {
                int r0 = wm + i * 16 + (lane >> 2);
                a[i][0] = As[r0 * SW + kk];
                a[i][1] = As[(r0 + 8) * SW + kk];
                a[i][2] = As[r0 * SW + kk + 4];
                a[i][3] = As[(r0 + 8) * SW + kk + 4];
            }
#pragma unroll
            for (int j = 0; j < NT; j++) {
                int n0 = wn + j * 8 + (lane >> 2);
                bfr[j][0] = Bs[n0 * SW + kk];
                bfr[j][1] = Bs[n0 * SW + kk + 4];
            }
#pragma unroll
            for (int i = 0; i < MT; i++)
#pragma unroll
                for (int j = 0; j < NT; j++) {
                    asm volatile(
                        "mma.sync.aligned.m16n8k8.row.col.f32.tf32.tf32.f32 "
                        "{%0,%1,%2,%3}, {%4,%5,%6,%7}, {%8,%9}, {%0,%1,%2,%3};"
                        : "+f"(c[i][j][0]), "+f"(c[i][j][1]),
                          "+f"(c[i][j][2]), "+f"(c[i][j][3])
                        : "r"(a[i][0]), "r"(a[i][1]), "r"(a[i][2]), "r"(a[i][3]),
                          "r"(bfr[j][0]), "r"(bfr[j][1]));
                }
        }
        __syncthreads();
    }

    // ---- epilogue: write C ----
#pragma unroll
    for (int i = 0; i < MT; i++) {
        int r0 = bm + wm + i * 16 + (lane >> 2);
#pragma unroll
        for (int j = 0; j < NT; j++) {
            int c0 = bn + wn + j * 8 + 2 * (lane & 3);
            float2 lo = make_float2(c[i][j][0], c[i][j][1]);
            float2 hi = make_float2(c[i][j][2], c[i][j][3]);
            *(float2*)(Cout + (size_t)r0 * Nn + c0)       = lo;
            *(float2*)(Cout + (size_t)(r0 + 8) * Nn + c0) = hi;
        }
    }
}

// ---------------------------------------------------------------------------
// Depthwise causal conv (k=4) + SiLU, both directions
// ---------------------------------------------------------------------------
__global__ void conv_silu_kernel(const float* __restrict__ w,
                                 const float* __restrict__ b) {
    size_t i   = (size_t)blockIdx.x * 256 + threadIdx.x;   // over 2*NROWS*CC
    int d      = (int)(i & (CC - 1));
    size_t rg  = i >> 8;                                   // dir*NROWS + g*L + l
    int dir    = rg >= (size_t)NROWS;
    size_t row = rg - (size_t)dir * NROWS;                 // g*L + l
    int l = (int)(row & (LL - 1));
    int g = (int)(row >> 12);
    float acc = b[d];
#pragma unroll
    for (int k = 0; k < 4; k++) {
        int ls = (dir == 0) ? (l - 3 + k) : (l + 3 - k);
        if (ls >= 0 && ls < LL)
            acc += w[d * 4 + k] * g_xz[((size_t)g * LL + ls) * (2 * CC) + d];
    }
    float sv = acc / (1.0f + __expf(-acc));
    g_xc[(size_t)dir * NROWS * CC + row * CC + d] = sv;
}

// ---------------------------------------------------------------------------
// dt_proj (K=16) + softplus, both directions. One block per row.
// ---------------------------------------------------------------------------
__global__ void dtproj_kernel(const float* __restrict__ dtw,
                              const float* __restrict__ dtb) {
    int row = blockIdx.x;
    int dir = blockIdx.y;
    const float* xr = g_xdbl + (size_t)dir * NROWS * 32 + (size_t)row * 32;
    float dt[RNK];
#pragma unroll
    for (int r = 0; r < RNK; r++) dt[r] = __ldg(xr + r);
    int d = threadIdx.x;
    float v = dtb[d];
#pragma unroll
    for (int r = 0; r < RNK; r++) v += dtw[d * RNK + r] * dt[r];
    v = (v > 20.f) ? v : log1pf(__expf(v));
    g_delta[(size_t)dir * NROWS * CC + (size_t)row * CC + d] = v;
}

// ---------------------------------------------------------------------------
// Selective scan, chunked (3 phases).
// ---------------------------------------------------------------------------
__global__ void scan_phase1(const float* __restrict__ Alog_f,
                            const float* __restrict__ Alog_b) {
    int c = blockIdx.x, g = blockIdx.y, dir = blockIdx.z;
    int d = threadIdx.x;
    const float* Alog = dir ? Alog_b : Alog_f;
    float A[NST];
#pragma unroll
    for (int n = 0; n < NST; n++) A[n] = -__expf(Alog[d * NST + n]);

    const float* del = g_delta + (size_t)dir * NROWS * CC;
    const float* uu_ = g_xc    + (size_t)dir * NROWS * CC;
    const float* xd  = g_xdbl  + (size_t)dir * NROWS * 32;

    float h[NST];
#pragma unroll
    for (int n = 0; n < NST; n++) h[n] = 0.f;
    float S = 0.f;

    for (int t = 0; t < LCH; t++) {
        int tau = c * LCH + t;
        int l   = (dir == 0) ? tau : (LL - 1 - tau);
        size_t row = (size_t)g * LL + l;
        float dl = del[row * CC + d];
        float uv = uu_[row * CC + d];
        S += dl;
        float du = dl * uv;
#pragma unroll
        for (int n = 0; n < NST; n++) {
            float Bn = __ldg(xd + row * 32 + 16 + n);
            h[n] = __expf(dl * A[n]) * h[n] + du * Bn;
        }
    }
    size_t base = ((size_t)dir * GG * NCH + (size_t)g * NCH + c) * CC + d;
#pragma unroll
    for (int n = 0; n < NST; n++) g_hloc[base * NST + n] = h[n];
    g_S[base] = S;
}

__global__ void scan_phase2(const float* __restrict__ Alog_f,
                            const float* __restrict__ Alog_b) {
    int t = blockIdx.x * 256 + threadIdx.x;   // 2*G*C*NST = 32768
    int n   = t & 7;
    int d   = (t >> 3) & 255;
    int g   = (t >> 11) & 7;
    int dir = t >> 14;
    const float* Alog = dir ? Alog_b : Alog_f;
    float A = -__expf(Alog[d * NST + n]);
    float h = 0.f;
    for (int c = 0; c < NCH; c++) {
        size_t base = ((size_t)dir * GG * NCH + (size_t)g * NCH + c) * CC + d;
        g_hini[base * NST + n] = h;
        float S = g_S[base];
        h = __expf(A * S) * h + g_hloc[base * NST + n];
    }
}

__global__ void scan_phase3(const float* __restrict__ Alog_f,
                            const float* __restrict__ Alog_b,
                            const float* __restrict__ Dp) {
    int c = blockIdx.x, g = blockIdx.y, dir = blockIdx.z;
    int d = threadIdx.x;
    const float* Alog = dir ? Alog_b : Alog_f;
    float A[NST];
#pragma unroll
    for (int n = 0; n < NST; n++) A[n] = -__expf(Alog[d * NST + n]);
    float Dv = Dp[d];

    const float* del = g_delta + (size_t)dir * NROWS * CC;
    const float* uu_ = g_xc    + (size_t)dir * NROWS * CC;
    const float* xd  = g_xdbl  + (size_t)dir * NROWS * 32;
    float* yo        = g_ydir  + (size_t)dir * NROWS * CC;

    size_t base = ((size_t)dir * GG * NCH + (size_t)g * NCH + c) * CC + d;
    float h[NST];
#pragma unroll
    for (int n = 0; n < NST; n++) h[n] = g_hini[base * NST + n];

    for (int t = 0; t < LCH; t++) {
        int tau = c * LCH + t;
        int l   = (dir == 0) ? tau : (LL - 1 - tau);
        size_t row = (size_t)g * LL + l;
        float dl = del[row * CC + d];
        float uv = uu_[row * CC + d];
        float du = dl * uv;
        float y  = 0.f;
#pragma unroll
        for (int n = 0; n < NST; n++) {
            float Bn = __ldg(xd + row * 32 + 16 + n);
            float Cn = __ldg(xd + row * 32 + 24 + n);
            h[n] = __expf(dl * A[n]) * h[n] + du * Bn;
            y += h[n] * Cn;
        }
        float z  = g_xz[row * (2 * CC) + CC + d];
        float sz = z / (1.0f + __expf(-z));
        yo[row * CC + d] = (y + Dv * uv) * sz;
    }
}

// ---------------------------------------------------------------------------
// Host launcher — kernel launches only.
// ---------------------------------------------------------------------------
extern "C" void kernel_launch(void* const* d_in, const int* in_sizes, int n_in,
                              void* d_out, int out_size) {
    const float* data  = (const float*)d_in[0];
    const float* ln_w  = (const float*)d_in[1];
    const float* ln_b  = (const float*)d_in[2];
    const float* inpw  = (const float*)d_in[3];
    const float* convw = (const float*)d_in[4];
    const float* convb = (const float*)d_in[5];
    const float* xprw  = (const float*)d_in[6];
    const float* dtw   = (const float*)d_in[7];
    const float* dtb   = (const float*)d_in[8];
    const float* Alog  = (const float*)d_in[9];
    const float* Ablog = (const float*)d_in[10];
    const float* Dmat  = (const float*)d_in[11];
    const float* outw  = (const float*)d_in[12];
    const float* mn_w  = (const float*)d_in[13];
    const float* mn_b  = (const float*)d_in[14];
    const int*   rl    = (const int*)  d_in[15];

    dim3 tposeGrid(LL / 32, CC / 32, GG);
    dim3 tposeBlk(32, 8);

    mean_kernel<<<tposeGrid, tposeBlk>>>(data, rl);

    for (int i = 0; i < DEPTHN; i++) {
        const float* lnw_i  = ln_w  + i * CC;
        const float* lnb_i  = ln_b  + i * CC;
        const float* inw_i  = inpw  + (size_t)i * 2 * CC * CC;
        const float* cw_i   = convw + i * CC * 4;
        const float* cb_i   = convb + i * CC;
        const float* xpw_i  = xprw  + (size_t)i * 32 * CC;
        const float* dtw_i  = dtw   + (size_t)i * CC * RNK;
        const float* dtb_i  = dtb   + i * CC;
        const float* Al_i   = Alog  + (size_t)i * CC * NST;
        const float* Ab_i   = Ablog + (size_t)i * CC * NST;
        const float* D_i    = Dmat  + i * CC;
        const float* ow_i   = outw  + (size_t)i * CC * CC;
        const float* mnw_i  = mn_w  + i * CC;
        const float* mnb_i  = mn_b  + i * CC;

        // 1. pre-LayerNorm:  g_x -> g_xn
        ln_kernel<0><<<NROWS / 8, 256>>>(lnw_i, lnb_i);
        // 2. in_proj (tf32 tensor cores): (32768x256)x(512x256)^T -> g_xz
        tc_gemm<0, 128, 128, 2, 4>
            <<<dim3(512 / 128, NROWS / 128), 256>>>(inw_i);
        // 3. causal conv + silu, both directions -> g_xc
        conv_silu_kernel<<<(2 * NROWS * CC) / 256, 256>>>(cw_i, cb_i);
        // 4. x_proj both directions (tensor cores, gridDim.z = 2) -> g_xdbl
        tc_gemm<1, 128, 32, 8, 1>
            <<<dim3(1, NROWS / 128, 2), 256>>>(xpw_i);
        // 5. dt_proj + softplus -> g_delta
        dtproj_kernel<<<dim3(NROWS, 2), 256>>>(dtw_i, dtb_i);
        // 6. chunked selective scan -> g_ydir
        scan_phase1<<<dim3(NCH, GG, 2), 256>>>(Al_i, Ab_i);
        scan_phase2<<<(2 * GG * CC * NST) / 256, 256>>>(Al_i, Ab_i);
        scan_phase3<<<dim3(NCH, GG, 2), 256>>>(Al_i, Ab_i, D_i);
        // 7. out_proj (tensor cores) with A = 0.5*(y_f + y_b) -> g_xn
        tc_gemm<2, 128, 128, 2, 4>
            <<<dim3(256 / 128, NROWS / 128), 256>>>(ow_i);
        // 8. post-norm + residual (in-place update of g_x)
        ln_kernel<1><<<NROWS / 8, 256>>>(mnw_i, mnb_i);
    }

    out_transpose<<<tposeGrid, tposeBlk>>>((float*)d_out);
}

// round 6
// speedup vs baseline: 2.5350x; 1.8488x over previous
#include <cuda_runtime.h>
#include <cstdint>

// ---------------------------------------------------------------------------
// Problem constants
// ---------------------------------------------------------------------------
#define GG      8
#define LL      4096
#define CC      256
#define NST     8
#define RNK     16
#define DEPTHN  4
#define NROWS   (GG*LL)
#define LCH     64
#define NCH     (LL/LCH)

// ---------------------------------------------------------------------------
// Scratch (device globals)
// ---------------------------------------------------------------------------
__device__ float g_x    [NROWS*CC];
__device__ float g_xn   [NROWS*CC];
__device__ float g_xz   [NROWS*2*CC];
__device__ float g_xc   [2*NROWS*CC];
__device__ float g_xdbl [2*NROWS*32];
__device__ float g_delta[2*NROWS*CC];
__device__ float g_ydir [2*NROWS*CC];   // phase3 writes 0.5*y*silu(z)
__device__ float g_hloc [2*GG*NCH*CC*NST];
__device__ float g_hini [2*GG*NCH*CC*NST];
__device__ float g_S    [2*GG*NCH*CC];

// ---------------------------------------------------------------------------
// mean + transpose: data (B,C,HW) -> g_x (g,l,c)
// ---------------------------------------------------------------------------
__global__ void mean_kernel(const float* __restrict__ data,
                            const int* __restrict__ rl) {
    __shared__ float tile[32][33];
    int g  = blockIdx.z;
    int c0 = blockIdx.y * 32;
    int l0 = blockIdx.x * 32;
    int off = 0;
    for (int i = 0; i < g; i++) off += rl[i];
    int cnt = rl[g];
    float inv = 1.0f / (float)cnt;
    for (int cc = threadIdx.y; cc < 32; cc += 8) {
        int c = c0 + cc;
        int l = l0 + threadIdx.x;
        float s = 0.f;
        for (int a = 0; a < cnt; a++)
            s += data[((size_t)(off + a) * CC + c) * LL + l];
        tile[cc][threadIdx.x] = s * inv;
    }
    __syncthreads();
    for (int lc = threadIdx.y; lc < 32; lc += 8) {
        int l = l0 + lc;
        int c = c0 + threadIdx.x;
        g_x[((size_t)g * LL + l) * CC + c] = tile[threadIdx.x][lc];
    }
}

__global__ void out_transpose(float* __restrict__ out) {
    __shared__ float tile[32][33];
    int g  = blockIdx.z;
    int c0 = blockIdx.y * 32;
    int l0 = blockIdx.x * 32;
    for (int lc = threadIdx.y; lc < 32; lc += 8)
        tile[threadIdx.x][lc] = g_x[((size_t)g * LL + l0 + lc) * CC + c0 + threadIdx.x];
    __syncthreads();
    for (int cc = threadIdx.y; cc < 32; cc += 8)
        out[((size_t)g * CC + c0 + cc) * LL + l0 + threadIdx.x] = tile[cc][threadIdx.x];
}

// ---------------------------------------------------------------------------
// LayerNorm (warp per row). MODE0: g_xn=LN(g_x)  MODE1: g_x=LN(g_xn)+g_x
// ---------------------------------------------------------------------------
template<int MODE>
__global__ void ln_kernel(const float* __restrict__ w,
                          const float* __restrict__ b) {
    int row  = blockIdx.x * 8 + (threadIdx.x >> 5);
    int lane = threadIdx.x & 31;
    const float* r = (MODE == 0 ? g_x : g_xn) + (size_t)row * CC;
    float v[8];
    float s = 0.f, s2 = 0.f;
#pragma unroll
    for (int k = 0; k < 8; k++) {
        v[k] = r[k * 32 + lane];
        s  += v[k];
        s2 += v[k] * v[k];
    }
#pragma unroll
    for (int o = 16; o; o >>= 1) {
        s  += __shfl_xor_sync(0xffffffffu, s,  o);
        s2 += __shfl_xor_sync(0xffffffffu, s2, o);
    }
    float mu  = s * (1.0f / CC);
    float var = s2 * (1.0f / CC) - mu * mu;
    float inv = rsqrtf(var + 1e-5f);
    float* o_ = (MODE == 0 ? g_xn : g_x) + (size_t)row * CC;
#pragma unroll
    for (int k = 0; k < 8; k++) {
        int cc = k * 32 + lane;
        float y = (v[k] - mu) * inv * w[cc] + b[cc];
        if (MODE == 1) y += g_x[(size_t)row * CC + cc];
        o_[cc] = y;
    }
}

// ---------------------------------------------------------------------------
// cp.async helpers
// ---------------------------------------------------------------------------
__device__ __forceinline__ void cp16(void* dst_smem, const void* src) {
    uint32_t d = (uint32_t)__cvta_generic_to_shared(dst_smem);
    asm volatile("cp.async.cg.shared.global [%0], [%1], 16;" :: "r"(d), "l"(src));
}
__device__ __forceinline__ unsigned f2tf(float x) {
    unsigned r;
    asm("cvt.rna.tf32.f32 %0, %1;" : "=r"(r) : "f"(x));
    return r;
}
#define CP_COMMIT() asm volatile("cp.async.commit_group;" ::: "memory")
#define CP_WAIT(n)  asm volatile("cp.async.wait_group %0;" :: "n"(n) : "memory")

// ---------------------------------------------------------------------------
// Pipelined tf32 tensor-core GEMM: Cout[m,n] = sum_k A[m,k]*W[n,k]
// BK=16, double-buffered cp.async, 8 warps.
// MODE 0: in_proj   A=g_xn,  C=g_xz  (Nn=512), K=256
// MODE 1: x_proj    A=g_xc + z*NROWS*CC, C=g_xdbl + z*NROWS*32 (Nn=32), K=256
// MODE 2: out_proj  virtual K=512: tiles 0..15 from y_f, 16..31 from y_b
//                   (phase3 pre-scaled by 0.5), C=g_xn (Nn=256)
// ---------------------------------------------------------------------------
template<int MODE, int BN>
__global__ void __launch_bounds__(256)
tc_gemm(const float* __restrict__ W) {
    constexpr int BM = 128;
    constexpr int BK = 16;
    constexpr int SW = BK + 4;                 // 20 floats: conflict-free
    constexpr int KT = (MODE == 2) ? 32 : 16;  // number of BK tiles
    constexpr int WARPS_N = (BN == 128) ? 4 : 1;
    constexpr int WARPS_M = 8 / WARPS_N;
    constexpr int WM = BM / WARPS_M;
    constexpr int WN = BN / WARPS_N;
    constexpr int MT = WM / 16;
    constexpr int NT = WN / 8;

    __shared__ float As[2][BM * SW];
    __shared__ float Bs[2][BN * SW];

    const int tid  = threadIdx.x;
    const int lane = tid & 31;
    const int warp = tid >> 5;
    const int bm   = blockIdx.y * BM;
    const int bn   = blockIdx.x * BN;
    const int wm   = (warp / WARPS_N) * WM;
    const int wn   = (warp % WARPS_N) * WN;

    const float* A0;
    float* Cout;
    int Nn;
    if (MODE == 0)      { A0 = g_xn;  Cout = g_xz;  Nn = 2 * CC; }
    else if (MODE == 1) { A0 = g_xc + (size_t)blockIdx.z * NROWS * CC;
                          Cout = g_xdbl + (size_t)blockIdx.z * NROWS * 32; Nn = 32; }
    else                { A0 = g_ydir; Cout = g_xn; Nn = CC; }

    auto stage = [&](int s, int kc) {
        const float* Ap = A0;
        if (MODE == 2 && kc >= 16) Ap = g_ydir + (size_t)NROWS * CC;
        const int k0 = (kc & 15) * BK;
        // A tile: BM rows x 16 floats = BM*4 16B chunks
        for (int idx = tid; idx < BM * 4; idx += 256) {
            int r = idx >> 2, q = idx & 3;
            cp16(&As[s][r * SW + q * 4], Ap + (size_t)(bm + r) * CC + k0 + q * 4);
        }
        for (int idx = tid; idx < BN * 4; idx += 256) {
            int r = idx >> 2, q = idx & 3;
            cp16(&Bs[s][r * SW + q * 4], W + (size_t)(bn + r) * CC + k0 + q * 4);
        }
    };

    float c[MT][NT][4];
#pragma unroll
    for (int i = 0; i < MT; i++)
#pragma unroll
        for (int j = 0; j < NT; j++)
#pragma unroll
            for (int q = 0; q < 4; q++) c[i][j][q] = 0.f;

    stage(0, 0);
    CP_COMMIT();

#pragma unroll 1
    for (int kc = 0; kc < KT; kc++) {
        if (kc + 1 < KT) {
            stage((kc + 1) & 1, kc + 1);
            CP_COMMIT();
            CP_WAIT(1);
        } else {
            CP_WAIT(0);
        }
        __syncthreads();

        const float* as_ = As[kc & 1];
        const float* bs_ = Bs[kc & 1];
#pragma unroll
        for (int ks = 0; ks < BK / 8; ks++) {
            const int kk = ks * 8 + (lane & 3);
            unsigned a[MT][4], bf[NT][2];
#pragma unroll
            for (int i = 0; i < MT; i++) {
                int r0 = wm + i * 16 + (lane >> 2);
                a[i][0] = f2tf(as_[r0 * SW + kk]);
                a[i][1] = f2tf(as_[(r0 + 8) * SW + kk]);
                a[i][2] = f2tf(as_[r0 * SW + kk + 4]);
                a[i][3] = f2tf(as_[(r0 + 8) * SW + kk + 4]);
            }
#pragma unroll
            for (int j = 0; j < NT; j++) {
                int n0 = wn + j * 8 + (lane >> 2);
                bf[j][0] = f2tf(bs_[n0 * SW + kk]);
                bf[j][1] = f2tf(bs_[n0 * SW + kk + 4]);
            }
#pragma unroll
            for (int i = 0; i < MT; i++)
#pragma unroll
                for (int j = 0; j < NT; j++) {
                    asm volatile(
                        "mma.sync.aligned.m16n8k8.row.col.f32.tf32.tf32.f32 "
                        "{%0,%1,%2,%3}, {%4,%5,%6,%7}, {%8,%9}, {%0,%1,%2,%3};"
                        : "+f"(c[i][j][0]), "+f"(c[i][j][1]),
                          "+f"(c[i][j][2]), "+f"(c[i][j][3])
                        : "r"(a[i][0]), "r"(a[i][1]), "r"(a[i][2]), "r"(a[i][3]),
                          "r"(bf[j][0]), "r"(bf[j][1]));
                }
        }
        __syncthreads();
    }

#pragma unroll
    for (int i = 0; i < MT; i++) {
        int r0 = bm + wm + i * 16 + (lane >> 2);
#pragma unroll
        for (int j = 0; j < NT; j++) {
            int c0 = bn + wn + j * 8 + 2 * (lane & 3);
            *(float2*)(Cout + (size_t)r0 * Nn + c0)       = make_float2(c[i][j][0], c[i][j][1]);
            *(float2*)(Cout + (size_t)(r0 + 8) * Nn + c0) = make_float2(c[i][j][2], c[i][j][3]);
        }
    }
}

// ---------------------------------------------------------------------------
// Depthwise causal conv (k=4) + SiLU, both directions
// ---------------------------------------------------------------------------
__global__ void conv_silu_kernel(const float* __restrict__ w,
                                 const float* __restrict__ b) {
    size_t i   = (size_t)blockIdx.x * 256 + threadIdx.x;
    int d      = (int)(i & (CC - 1));
    size_t rg  = i >> 8;
    int dir    = rg >= (size_t)NROWS;
    size_t row = rg - (size_t)dir * NROWS;
    int l = (int)(row & (LL - 1));
    int g = (int)(row >> 12);
    float acc = b[d];
#pragma unroll
    for (int k = 0; k < 4; k++) {
        int ls = (dir == 0) ? (l - 3 + k) : (l + 3 - k);
        if (ls >= 0 && ls < LL)
            acc += w[d * 4 + k] * g_xz[((size_t)g * LL + ls) * (2 * CC) + d];
    }
    float sv = acc / (1.0f + __expf(-acc));
    g_xc[(size_t)dir * NROWS * CC + row * CC + d] = sv;
}

// ---------------------------------------------------------------------------
// dt_proj + softplus. 64 rows per block; weights cached (transposed) in smem.
// ---------------------------------------------------------------------------
__global__ void dtproj_kernel(const float* __restrict__ dtw,
                              const float* __restrict__ dtb) {
    __shared__ float swt[RNK][CC];        // dtw transposed: [r][d]
    __shared__ float sdt[64][RNK + 1];    // dt inputs for 64 rows
    const int d   = threadIdx.x;
    const int dir = blockIdx.y;
    const size_t row0 = (size_t)blockIdx.x * 64;

    for (int i = threadIdx.x; i < CC * RNK; i += 256) {
        int dd = i >> 4, r = i & 15;
        swt[r][dd] = dtw[i];
    }
    const float* xb = g_xdbl + (size_t)dir * NROWS * 32 + row0 * 32;
    for (int i = threadIdx.x; i < 64 * RNK; i += 256) {
        int t = i >> 4, r = i & 15;
        sdt[t][r] = xb[t * 32 + r];
    }
    __syncthreads();

    float wr[RNK];
#pragma unroll
    for (int r = 0; r < RNK; r++) wr[r] = swt[r][d];
    const float bv = dtb[d];
    float* out = g_delta + (size_t)dir * NROWS * CC + row0 * CC + d;
    for (int t = 0; t < 64; t++) {
        float v = bv;
#pragma unroll
        for (int r = 0; r < RNK; r++) v += wr[r] * sdt[t][r];
        v = (v > 20.f) ? v : log1pf(__expf(v));
        out[t * CC] = v;
    }
}

// ---------------------------------------------------------------------------
// Selective scan, chunked (3 phases)
// ---------------------------------------------------------------------------
__global__ void scan_phase1(const float* __restrict__ Alog_f,
                            const float* __restrict__ Alog_b) {
    int c = blockIdx.x, g = blockIdx.y, dir = blockIdx.z;
    int d = threadIdx.x;
    const float* Alog = dir ? Alog_b : Alog_f;
    float A[NST];
#pragma unroll
    for (int n = 0; n < NST; n++) A[n] = -__expf(Alog[d * NST + n]);

    const float* del = g_delta + (size_t)dir * NROWS * CC;
    const float* uu_ = g_xc    + (size_t)dir * NROWS * CC;
    const float* xd  = g_xdbl  + (size_t)dir * NROWS * 32;

    float h[NST];
#pragma unroll
    for (int n = 0; n < NST; n++) h[n] = 0.f;
    float S = 0.f;

    for (int t = 0; t < LCH; t++) {
        int tau = c * LCH + t;
        int l   = (dir == 0) ? tau : (LL - 1 - tau);
        size_t row = (size_t)g * LL + l;
        float dl = del[row * CC + d];
        float uv = uu_[row * CC + d];
        S += dl;
        float du = dl * uv;
#pragma unroll
        for (int n = 0; n < NST; n++) {
            float Bn = __ldg(xd + row * 32 + 16 + n);
            h[n] = __expf(dl * A[n]) * h[n] + du * Bn;
        }
    }
    size_t base = ((size_t)dir * GG * NCH + (size_t)g * NCH + c) * CC + d;
#pragma unroll
    for (int n = 0; n < NST; n++) g_hloc[base * NST + n] = h[n];
    g_S[base] = S;
}

__global__ void scan_phase2(const float* __restrict__ Alog_f,
                            const float* __restrict__ Alog_b) {
    int t = blockIdx.x * 256 + threadIdx.x;
    int n   = t & 7;
    int d   = (t >> 3) & 255;
    int g   = (t >> 11) & 7;
    int dir = t >> 14;
    const float* Alog = dir ? Alog_b : Alog_f;
    float A = -__expf(Alog[d * NST + n]);
    float h = 0.f;
    for (int c = 0; c < NCH; c++) {
        size_t base = ((size_t)dir * GG * NCH + (size_t)g * NCH + c) * CC + d;
        g_hini[base * NST + n] = h;
        float S = g_S[base];
        h = __expf(A * S) * h + g_hloc[base * NST + n];
    }
}

__global__ void scan_phase3(const float* __restrict__ Alog_f,
                            const float* __restrict__ Alog_b,
                            const float* __restrict__ Dp) {
    int c = blockIdx.x, g = blockIdx.y, dir = blockIdx.z;
    int d = threadIdx.x;
    const float* Alog = dir ? Alog_b : Alog_f;
    float A[NST];
#pragma unroll
    for (int n = 0; n < NST; n++) A[n] = -__expf(Alog[d * NST + n]);
    float Dv = Dp[d];

    const float* del = g_delta + (size_t)dir * NROWS * CC;
    const float* uu_ = g_xc    + (size_t)dir * NROWS * CC;
    const float* xd  = g_xdbl  + (size_t)dir * NROWS * 32;
    float* yo        = g_ydir  + (size_t)dir * NROWS * CC;

    size_t base = ((size_t)dir * GG * NCH + (size_t)g * NCH + c) * CC + d;
    float h[NST];
#pragma unroll
    for (int n = 0; n < NST; n++) h[n] = g_hini[base * NST + n];

    for (int t = 0; t < LCH; t++) {
        int tau = c * LCH + t;
        int l   = (dir == 0) ? tau : (LL - 1 - tau);
        size_t row = (size_t)g * LL + l;
        float dl = del[row * CC + d];
        float uv = uu_[row * CC + d];
        float du = dl * uv;
        float y  = 0.f;
#pragma unroll
        for (int n = 0; n < NST; n++) {
            float Bn = __ldg(xd + row * 32 + 16 + n);
            float Cn = __ldg(xd + row * 32 + 24 + n);
            h[n] = __expf(dl * A[n]) * h[n] + du * Bn;
            y += h[n] * Cn;
        }
        float z  = g_xz[row * (2 * CC) + CC + d];
        float sz = z / (1.0f + __expf(-z));
        // 0.5 factor folded in here (out_proj sums the two directions)
        yo[row * CC + d] = 0.5f * (y + Dv * uv) * sz;
    }
}

// ---------------------------------------------------------------------------
// Host launcher — kernel launches only.
// ---------------------------------------------------------------------------
extern "C" void kernel_launch(void* const* d_in, const int* in_sizes, int n_in,
                              void* d_out, int out_size) {
    const float* data  = (const float*)d_in[0];
    const float* ln_w  = (const float*)d_in[1];
    const float* ln_b  = (const float*)d_in[2];
    const float* inpw  = (const float*)d_in[3];
    const float* convw = (const float*)d_in[4];
    const float* convb = (const float*)d_in[5];
    const float* xprw  = (const float*)d_in[6];
    const float* dtw   = (const float*)d_in[7];
    const float* dtb   = (const float*)d_in[8];
    const float* Alog  = (const float*)d_in[9];
    const float* Ablog = (const float*)d_in[10];
    const float* Dmat  = (const float*)d_in[11];
    const float* outw  = (const float*)d_in[12];
    const float* mn_w  = (const float*)d_in[13];
    const float* mn_b  = (const float*)d_in[14];
    const int*   rl    = (const int*)  d_in[15];

    dim3 tposeGrid(LL / 32, CC / 32, GG);
    dim3 tposeBlk(32, 8);

    mean_kernel<<<tposeGrid, tposeBlk>>>(data, rl);

    for (int i = 0; i < DEPTHN; i++) {
        const float* lnw_i  = ln_w  + i * CC;
        const float* lnb_i  = ln_b  + i * CC;
        const float* inw_i  = inpw  + (size_t)i * 2 * CC * CC;
        const float* cw_i   = convw + i * CC * 4;
        const float* cb_i   = convb + i * CC;
        const float* xpw_i  = xprw  + (size_t)i * 32 * CC;
        const float* dtw_i  = dtw   + (size_t)i * CC * RNK;
        const float* dtb_i  = dtb   + i * CC;
        const float* Al_i   = Alog  + (size_t)i * CC * NST;
        const float* Ab_i   = Ablog + (size_t)i * CC * NST;
        const float* D_i    = Dmat  + i * CC;
        const float* ow_i   = outw  + (size_t)i * CC * CC;
        const float* mnw_i  = mn_w  + i * CC;
        const float* mnb_i  = mn_b  + i * CC;

        // 1. pre-LayerNorm
        ln_kernel<0><<<NROWS / 8, 256>>>(lnw_i, lnb_i);
        // 2. in_proj (pipelined tf32 mma): (32768x256)x(512x256)^T -> g_xz
        tc_gemm<0, 128><<<dim3(512 / 128, NROWS / 128), 256>>>(inw_i);
        // 3. causal conv + silu
        conv_silu_kernel<<<(2 * NROWS * CC) / 256, 256>>>(cw_i, cb_i);
        // 4. x_proj both directions -> g_xdbl
        tc_gemm<1, 32><<<dim3(1, NROWS / 128, 2), 256>>>(xpw_i);
        // 5. dt_proj + softplus
        dtproj_kernel<<<dim3(NROWS / 64, 2), 256>>>(dtw_i, dtb_i);
        // 6. chunked selective scan
        scan_phase1<<<dim3(NCH, GG, 2), 256>>>(Al_i, Ab_i);
        scan_phase2<<<(2 * GG * CC * NST) / 256, 256>>>(Al_i, Ab_i);
        scan_phase3<<<dim3(NCH, GG, 2), 256>>>(Al_i, Ab_i, D_i);
        // 7. out_proj (K-doubled: sums 0.5*y_f·W + 0.5*y_b·W) -> g_xn
        tc_gemm<2, 128><<<dim3(256 / 128, NROWS / 128), 256>>>(ow_i);
        // 8. post-norm + residual
        ln_kernel<1><<<NROWS / 8, 256>>>(mnw_i, mnb_i);
    }

    out_transpose<<<tposeGrid, tposeBlk>>>((float*)d_out);
}

// round 8
// speedup vs baseline: 2.6217x; 1.0342x over previous
#include <cuda_runtime.h>
#include <cstdint>

// ---------------------------------------------------------------------------
// Problem constants
// ---------------------------------------------------------------------------
#define GG      8
#define LL      4096
#define CC      256
#define NST     8
#define RNK     16
#define DEPTHN  4
#define NROWS   (GG*LL)
#define LCH     64
#define NCH     (LL/LCH)

// ---------------------------------------------------------------------------
// Scratch (device globals) — referenced ONLY from device code
// ---------------------------------------------------------------------------
__device__ float g_x    [NROWS*CC];
__device__ float g_xn   [NROWS*CC];
__device__ float g_xz   [NROWS*2*CC];
__device__ float g_xc   [2*NROWS*CC];
__device__ float g_xdbl [2*NROWS*32];
__device__ float g_delta[2*NROWS*CC];
__device__ float g_ydir [2*NROWS*CC];
__device__ float g_hloc [2*GG*NCH*CC*NST];
__device__ float g_hini [2*GG*NCH*CC*NST];
__device__ float g_S    [2*GG*NCH*CC];
__device__ float g_win  [DEPTHN*2*CC*CC];
__device__ float g_wxp  [DEPTHN*32*CC];
__device__ float g_wout [DEPTHN*CC*CC];

__device__ __forceinline__ unsigned f2tf(float x) {
    unsigned r;
    asm("cvt.rna.tf32.f32 %0, %1;" : "=r"(r) : "f"(x));
    return r;
}
__device__ __forceinline__ float tf32r(float x) { return __uint_as_float(f2tf(x)); }

// ---------------------------------------------------------------------------
// one-shot weight prep: round all layers' GEMM weights to tf32
// ---------------------------------------------------------------------------
#define NIN  (DEPTHN*2*CC*CC)
#define NXP  (DEPTHN*32*CC)
#define NOUT (DEPTHN*CC*CC)
__global__ void wprep(const float* __restrict__ inpw,
                      const float* __restrict__ xpw,
                      const float* __restrict__ outw) {
    int i = blockIdx.x * 256 + threadIdx.x;
    if (i < NIN)                    g_win[i]          = tf32r(inpw[i]);
    else if (i < NIN + NXP)         g_wxp[i - NIN]    = tf32r(xpw[i - NIN]);
    else if (i < NIN + NXP + NOUT)  g_wout[i-NIN-NXP] = tf32r(outw[i-NIN-NXP]);
}

// ---------------------------------------------------------------------------
// mean + transpose: data (B,C,HW) -> g_x (g,l,c)
// ---------------------------------------------------------------------------
__global__ void mean_kernel(const float* __restrict__ data,
                            const int* __restrict__ rl) {
    __shared__ float tile[32][33];
    int g  = blockIdx.z;
    int c0 = blockIdx.y * 32;
    int l0 = blockIdx.x * 32;
    int off = 0;
    for (int i = 0; i < g; i++) off += rl[i];
    int cnt = rl[g];
    float inv = 1.0f / (float)cnt;
    for (int cc = threadIdx.y; cc < 32; cc += 8) {
        int c = c0 + cc;
        int l = l0 + threadIdx.x;
        float s = 0.f;
        for (int a = 0; a < cnt; a++)
            s += data[((size_t)(off + a) * CC + c) * LL + l];
        tile[cc][threadIdx.x] = s * inv;
    }
    __syncthreads();
    for (int lc = threadIdx.y; lc < 32; lc += 8) {
        int l = l0 + lc;
        int c = c0 + threadIdx.x;
        g_x[((size_t)g * LL + l) * CC + c] = tile[threadIdx.x][lc];
    }
}

__global__ void out_transpose(float* __restrict__ out) {
    __shared__ float tile[32][33];
    int g  = blockIdx.z;
    int c0 = blockIdx.y * 32;
    int l0 = blockIdx.x * 32;
    for (int lc = threadIdx.y; lc < 32; lc += 8)
        tile[threadIdx.x][lc] = g_x[((size_t)g * LL + l0 + lc) * CC + c0 + threadIdx.x];
    __syncthreads();
    for (int cc = threadIdx.y; cc < 32; cc += 8)
        out[((size_t)g * CC + c0 + cc) * LL + l0 + threadIdx.x] = tile[cc][threadIdx.x];
}

// ---------------------------------------------------------------------------
// Fused LayerNorm (warp per row).
// POST: x := LN(g_xn)*wp+bp + g_x ; PRE: g_xn := tf32(LN(x)*wq+bq)
// ---------------------------------------------------------------------------
template<int POST, int PRE>
__global__ void ln_fused(const float* __restrict__ wp, const float* __restrict__ bp,
                         const float* __restrict__ wq, const float* __restrict__ bq) {
    int row  = blockIdx.x * 8 + (threadIdx.x >> 5);
    int lane = threadIdx.x & 31;
    float v[8];
    if (POST) {
        const float* r = g_xn + (size_t)row * CC;
        float s = 0.f, s2 = 0.f;
#pragma unroll
        for (int k = 0; k < 8; k++) {
            v[k] = r[k * 32 + lane];
            s += v[k]; s2 += v[k] * v[k];
        }
#pragma unroll
        for (int o = 16; o; o >>= 1) {
            s  += __shfl_xor_sync(0xffffffffu, s,  o);
            s2 += __shfl_xor_sync(0xffffffffu, s2, o);
        }
        float mu  = s * (1.0f / CC);
        float var = s2 * (1.0f / CC) - mu * mu;
        float inv = rsqrtf(var + 1e-5f);
#pragma unroll
        for (int k = 0; k < 8; k++) {
            int cc = k * 32 + lane;
            v[k] = (v[k] - mu) * inv * wp[cc] + bp[cc] + g_x[(size_t)row * CC + cc];
            g_x[(size_t)row * CC + cc] = v[k];
        }
    } else {
        const float* r = g_x + (size_t)row * CC;
#pragma unroll
        for (int k = 0; k < 8; k++) v[k] = r[k * 32 + lane];
    }
    if (PRE) {
        float s = 0.f, s2 = 0.f;
#pragma unroll
        for (int k = 0; k < 8; k++) { s += v[k]; s2 += v[k] * v[k]; }
#pragma unroll
        for (int o = 16; o; o >>= 1) {
            s  += __shfl_xor_sync(0xffffffffu, s,  o);
            s2 += __shfl_xor_sync(0xffffffffu, s2, o);
        }
        float mu  = s * (1.0f / CC);
        float var = s2 * (1.0f / CC) - mu * mu;
        float inv = rsqrtf(var + 1e-5f);
#pragma unroll
        for (int k = 0; k < 8; k++) {
            int cc = k * 32 + lane;
            g_xn[(size_t)row * CC + cc] = tf32r((v[k] - mu) * inv * wq[cc] + bq[cc]);
        }
    }
}

// ---------------------------------------------------------------------------
// cp.async helpers
// ---------------------------------------------------------------------------
__device__ __forceinline__ void cp16(void* dst_smem, const void* src) {
    uint32_t d = (uint32_t)__cvta_generic_to_shared(dst_smem);
    asm volatile("cp.async.cg.shared.global [%0], [%1], 16;" :: "r"(d), "l"(src));
}
#define CP_COMMIT() asm volatile("cp.async.commit_group;" ::: "memory")
#define CP_WAIT(n)  asm volatile("cp.async.wait_group %0;" :: "n"(n) : "memory")

// ---------------------------------------------------------------------------
// 3-stage pipelined tf32 tensor-core GEMM. Weight pointer computed from the
// layer index IN DEVICE CODE (device-global symbols are invalid host-side).
// MODE 0: in_proj   A=g_xn,  W=g_win[layer],  C=g_xz  (Nn=512), KT=16
// MODE 1: x_proj    A=g_xc+z*NROWS*CC (cvt), W=g_wxp[layer], C=g_xdbl.., KT=16
// MODE 2: out_proj  virtual K=512 over ydir fwd|bwd, W=g_wout[layer], KT=32
// ---------------------------------------------------------------------------
template<int MODE, int BN>
__global__ void __launch_bounds__(256)
tc_gemm(int layer) {
    constexpr int BM = 128;
    constexpr int BK = 16;
    constexpr int SW = BK + 4;
    constexpr int KT = (MODE == 2) ? 32 : 16;
    constexpr bool CVT_A = (MODE == 1);
    constexpr int WARPS_N = (BN == 128) ? 4 : 1;
    constexpr int WARPS_M = 8 / WARPS_N;
    constexpr int WM = BM / WARPS_M;
    constexpr int WN = BN / WARPS_N;
    constexpr int MT = WM / 16;
    constexpr int NT = WN / 8;

    __shared__ float As[3][BM * SW];
    __shared__ float Bs[3][BN * SW];

    const int tid  = threadIdx.x;
    const int lane = tid & 31;
    const int warp = tid >> 5;
    const int bm   = blockIdx.y * BM;
    const int bn   = blockIdx.x * BN;
    const int wm   = (warp / WARPS_N) * WM;
    const int wn   = (warp % WARPS_N) * WN;

    const float* A0;
    const float* W;
    float* Cout;
    int Nn;
    if (MODE == 0)      { A0 = g_xn;  W = g_win + (size_t)layer * 2 * CC * CC;
                          Cout = g_xz;  Nn = 2 * CC; }
    else if (MODE == 1) { A0 = g_xc + (size_t)blockIdx.z * NROWS * CC;
                          W = g_wxp + (size_t)layer * 32 * CC;
                          Cout = g_xdbl + (size_t)blockIdx.z * NROWS * 32; Nn = 32; }
    else                { A0 = g_ydir; W = g_wout + (size_t)layer * CC * CC;
                          Cout = g_xn; Nn = CC; }

    auto stage = [&](int s, int kc) {
        const float* Ap = A0;
        if (MODE == 2 && kc >= 16) Ap = g_ydir + (size_t)NROWS * CC;
        const int k0 = (kc & 15) * BK;
        for (int idx = tid; idx < BM * 4; idx += 256) {
            int r = idx >> 2, q = idx & 3;
            cp16(&As[s][r * SW + q * 4], Ap + (size_t)(bm + r) * CC + k0 + q * 4);
        }
        for (int idx = tid; idx < BN * 4; idx += 256) {
            int r = idx >> 2, q = idx & 3;
            cp16(&Bs[s][r * SW + q * 4], W + (size_t)(bn + r) * CC + k0 + q * 4);
        }
    };

    float c[MT][NT][4];
#pragma unroll
    for (int i = 0; i < MT; i++)
#pragma unroll
        for (int j = 0; j < NT; j++)
#pragma unroll
            for (int q = 0; q < 4; q++) c[i][j][q] = 0.f;

    stage(0, 0); CP_COMMIT();
    stage(1, 1); CP_COMMIT();

#pragma unroll 1
    for (int kc = 0; kc < KT; kc++) {
        if (kc == KT - 1) { CP_WAIT(0); } else { CP_WAIT(1); }
        __syncthreads();

        const float* as_ = As[kc % 3];
        const float* bs_ = Bs[kc % 3];
#pragma unroll
        for (int ks = 0; ks < BK / 8; ks++) {
            const int kk = ks * 8 + (lane & 3);
            unsigned a[MT][4], bf[NT][2];
#pragma unroll
            for (int i = 0; i < MT; i++) {
                int r0 = wm + i * 16 + (lane >> 2);
                if (CVT_A) {
                    a[i][0] = f2tf(as_[r0 * SW + kk]);
                    a[i][1] = f2tf(as_[(r0 + 8) * SW + kk]);
                    a[i][2] = f2tf(as_[r0 * SW + kk + 4]);
                    a[i][3] = f2tf(as_[(r0 + 8) * SW + kk + 4]);
                } else {
                    a[i][0] = __float_as_uint(as_[r0 * SW + kk]);
                    a[i][1] = __float_as_uint(as_[(r0 + 8) * SW + kk]);
                    a[i][2] = __float_as_uint(as_[r0 * SW + kk + 4]);
                    a[i][3] = __float_as_uint(as_[(r0 + 8) * SW + kk + 4]);
                }
            }
#pragma unroll
            for (int j = 0; j < NT; j++) {
                int n0 = wn + j * 8 + (lane >> 2);
                bf[j][0] = __float_as_uint(bs_[n0 * SW + kk]);
                bf[j][1] = __float_as_uint(bs_[n0 * SW + kk + 4]);
            }
#pragma unroll
            for (int i = 0; i < MT; i++)
#pragma unroll
                for (int j = 0; j < NT; j++) {
                    asm volatile(
                        "mma.sync.aligned.m16n8k8.row.col.f32.tf32.tf32.f32 "
                        "{%0,%1,%2,%3}, {%4,%5,%6,%7}, {%8,%9}, {%0,%1,%2,%3};"
                        : "+f"(c[i][j][0]), "+f"(c[i][j][1]),
                          "+f"(c[i][j][2]), "+f"(c[i][j][3])
                        : "r"(a[i][0]), "r"(a[i][1]), "r"(a[i][2]), "r"(a[i][3]),
                          "r"(bf[j][0]), "r"(bf[j][1]));
                }
        }
        __syncthreads();
        if (kc + 2 < KT) { stage((kc + 2) % 3, kc + 2); CP_COMMIT(); }
    }

#pragma unroll
    for (int i = 0; i < MT; i++) {
        int r0 = bm + wm + i * 16 + (lane >> 2);
#pragma unroll
        for (int j = 0; j < NT; j++) {
            int c0 = bn + wn + j * 8 + 2 * (lane & 3);
            *(float2*)(Cout + (size_t)r0 * Nn + c0)       = make_float2(c[i][j][0], c[i][j][1]);
            *(float2*)(Cout + (size_t)(r0 + 8) * Nn + c0) = make_float2(c[i][j][2], c[i][j][3]);
        }
    }
}

// ---------------------------------------------------------------------------
// Depthwise causal conv (k=4) + SiLU, float4 over channels
// ---------------------------------------------------------------------------
__global__ void conv_silu_kernel(const float* __restrict__ w,
                                 const float* __restrict__ b) {
    size_t i  = (size_t)blockIdx.x * 256 + threadIdx.x;   // over 2*NROWS*CC/4
    int d0    = (int)(i & 63) * 4;
    size_t rg = i >> 6;
    int dir   = rg >= (size_t)NROWS;
    size_t row = rg - (size_t)dir * NROWS;
    int l = (int)(row & (LL - 1));
    int g = (int)(row >> 12);

    float4 wt[4];
#pragma unroll
    for (int j = 0; j < 4; j++) wt[j] = *(const float4*)(w + (d0 + j) * 4);
    float4 acc = *(const float4*)(b + d0);

#pragma unroll
    for (int k = 0; k < 4; k++) {
        int ls = (dir == 0) ? (l - 3 + k) : (l + 3 - k);
        if (ls >= 0 && ls < LL) {
            const float4 xv = *(const float4*)(g_xz + ((size_t)g * LL + ls) * (2 * CC) + d0);
            acc.x += ((const float*)&wt[0])[k] * xv.x;
            acc.y += ((const float*)&wt[1])[k] * xv.y;
            acc.z += ((const float*)&wt[2])[k] * xv.z;
            acc.w += ((const float*)&wt[3])[k] * xv.w;
        }
    }
    acc.x = acc.x / (1.0f + __expf(-acc.x));
    acc.y = acc.y / (1.0f + __expf(-acc.y));
    acc.z = acc.z / (1.0f + __expf(-acc.z));
    acc.w = acc.w / (1.0f + __expf(-acc.w));
    *(float4*)(g_xc + (size_t)dir * NROWS * CC + row * CC + d0) = acc;
}

// ---------------------------------------------------------------------------
// dt_proj + softplus (weights cached in smem, 64 rows/block)
// ---------------------------------------------------------------------------
__global__ void dtproj_kernel(const float* __restrict__ dtw,
                              const float* __restrict__ dtb) {
    __shared__ float swt[RNK][CC];
    __shared__ float sdt[64][RNK + 1];
    const int d   = threadIdx.x;
    const int dir = blockIdx.y;
    const size_t row0 = (size_t)blockIdx.x * 64;

    for (int i = threadIdx.x; i < CC * RNK; i += 256) {
        int dd = i >> 4, r = i & 15;
        swt[r][dd] = dtw[i];
    }
    const float* xb = g_xdbl + (size_t)dir * NROWS * 32 + row0 * 32;
    for (int i = threadIdx.x; i < 64 * RNK; i += 256) {
        int t = i >> 4, r = i & 15;
        sdt[t][r] = xb[t * 32 + r];
    }
    __syncthreads();

    float wr[RNK];
#pragma unroll
    for (int r = 0; r < RNK; r++) wr[r] = swt[r][d];
    const float bv = dtb[d];
    float* out = g_delta + (size_t)dir * NROWS * CC + row0 * CC + d;
    for (int t = 0; t < 64; t++) {
        float v = bv;
#pragma unroll
        for (int r = 0; r < RNK; r++) v += wr[r] * sdt[t][r];
        v = (v > 20.f) ? v : log1pf(__expf(v));
        out[t * CC] = v;
    }
}

// ---------------------------------------------------------------------------
// Selective scan. exp-collapse fast path: if A[n] == (n+1)*A[0] (runtime-
// verified), exp(dl*A[n]) = p^(n+1) with p = exp(dl*A[0]).
// ---------------------------------------------------------------------------
__device__ __forceinline__ bool a_struct(const float* A) {
    bool f = true;
#pragma unroll
    for (int n = 1; n < NST; n++)
        f &= fabsf(A[n] - (float)(n + 1) * A[0]) <= 1e-5f * (float)(n + 1) * fabsf(A[0]);
    return f;
}

template<bool FAST>
__device__ __forceinline__ void scan1_body(int c, int g, int dir, int d,
                                           const float* A, float* h, float& S) {
    const float* del = g_delta + (size_t)dir * NROWS * CC;
    const float* uu_ = g_xc    + (size_t)dir * NROWS * CC;
    const float* xd  = g_xdbl  + (size_t)dir * NROWS * 32;
    const float A0 = A[0];
    for (int t = 0; t < LCH; t++) {
        int tau = c * LCH + t;
        int l   = (dir == 0) ? tau : (LL - 1 - tau);
        size_t row = (size_t)g * LL + l;
        float dl = del[row * CC + d];
        float uv = uu_[row * CC + d];
        S += dl;
        float du = dl * uv;
        if (FAST) {
            float p = __expf(dl * A0);
            float e = p;
#pragma unroll
            for (int n = 0; n < NST; n++) {
                float Bn = __ldg(xd + row * 32 + 16 + n);
                h[n] = e * h[n] + du * Bn;
                e *= p;
            }
        } else {
#pragma unroll
            for (int n = 0; n < NST; n++) {
                float Bn = __ldg(xd + row * 32 + 16 + n);
                h[n] = __expf(dl * A[n]) * h[n] + du * Bn;
            }
        }
    }
}

__global__ void scan_phase1(const float* __restrict__ Alog_f,
                            const float* __restrict__ Alog_b) {
    int c = blockIdx.x, g = blockIdx.y, dir = blockIdx.z;
    int d = threadIdx.x;
    const float* Alog = dir ? Alog_b : Alog_f;
    float A[NST];
#pragma unroll
    for (int n = 0; n < NST; n++) A[n] = -__expf(Alog[d * NST + n]);
    float h[NST];
#pragma unroll
    for (int n = 0; n < NST; n++) h[n] = 0.f;
    float S = 0.f;

    if (a_struct(A)) scan1_body<true>(c, g, dir, d, A, h, S);
    else             scan1_body<false>(c, g, dir, d, A, h, S);

    size_t base = ((size_t)dir * GG * NCH + (size_t)g * NCH + c) * CC + d;
#pragma unroll
    for (int n = 0; n < NST; n++) g_hloc[base * NST + n] = h[n];
    g_S[base] = S;
}

__global__ void scan_phase2(const float* __restrict__ Alog_f,
                            const float* __restrict__ Alog_b) {
    int t = blockIdx.x * 256 + threadIdx.x;
    int n   = t & 7;
    int d   = (t >> 3) & 255;
    int g   = (t >> 11) & 7;
    int dir = t >> 14;
    const float* Alog = dir ? Alog_b : Alog_f;
    float A = -__expf(Alog[d * NST + n]);
    float h = 0.f;
    for (int c = 0; c < NCH; c++) {
        size_t base = ((size_t)dir * GG * NCH + (size_t)g * NCH + c) * CC + d;
        g_hini[base * NST + n] = h;
        float S = g_S[base];
        h = __expf(A * S) * h + g_hloc[base * NST + n];
    }
}

template<bool FAST>
__device__ __forceinline__ void scan3_body(int c, int g, int dir, int d,
                                           const float* A, float* h, float Dv) {
    const float* del = g_delta + (size_t)dir * NROWS * CC;
    const float* uu_ = g_xc    + (size_t)dir * NROWS * CC;
    const float* xd  = g_xdbl  + (size_t)dir * NROWS * 32;
    float* yo        = g_ydir  + (size_t)dir * NROWS * CC;
    const float A0 = A[0];
    for (int t = 0; t < LCH; t++) {
        int tau = c * LCH + t;
        int l   = (dir == 0) ? tau : (LL - 1 - tau);
        size_t row = (size_t)g * LL + l;
        float dl = del[row * CC + d];
        float uv = uu_[row * CC + d];
        float du = dl * uv;
        float y  = 0.f;
        if (FAST) {
            float p = __expf(dl * A0);
            float e = p;
#pragma unroll
            for (int n = 0; n < NST; n++) {
                float Bn = __ldg(xd + row * 32 + 16 + n);
                float Cn = __ldg(xd + row * 32 + 24 + n);
                h[n] = e * h[n] + du * Bn;
                y += h[n] * Cn;
                e *= p;
            }
        } else {
#pragma unroll
            for (int n = 0; n < NST; n++) {
                float Bn = __ldg(xd + row * 32 + 16 + n);
                float Cn = __ldg(xd + row * 32 + 24 + n);
                h[n] = __expf(dl * A[n]) * h[n] + du * Bn;
                y += h[n] * Cn;
            }
        }
        float z  = g_xz[row * (2 * CC) + CC + d];
        float sz = z / (1.0f + __expf(-z));
        yo[row * CC + d] = tf32r(0.5f * (y + Dv * uv) * sz);
    }
}

__global__ void scan_phase3(const float* __restrict__ Alog_f,
                            const float* __restrict__ Alog_b,
                            const float* __restrict__ Dp) {
    int c = blockIdx.x, g = blockIdx.y, dir = blockIdx.z;
    int d = threadIdx.x;
    const float* Alog = dir ? Alog_b : Alog_f;
    float A[NST];
#pragma unroll
    for (int n = 0; n < NST; n++) A[n] = -__expf(Alog[d * NST + n]);
    float Dv = Dp[d];
    size_t base = ((size_t)dir * GG * NCH + (size_t)g * NCH + c) * CC + d;
    float h[NST];
#pragma unroll
    for (int n = 0; n < NST; n++) h[n] = g_hini[base * NST + n];

    if (a_struct(A)) scan3_body<true>(c, g, dir, d, A, h, Dv);
    else             scan3_body<false>(c, g, dir, d, A, h, Dv);
}

// ---------------------------------------------------------------------------
// Host launcher — kernel launches only; device-global symbols never touched
// host-side.
// ---------------------------------------------------------------------------
extern "C" void kernel_launch(void* const* d_in, const int* in_sizes, int n_in,
                              void* d_out, int out_size) {
    const float* data  = (const float*)d_in[0];
    const float* ln_w  = (const float*)d_in[1];
    const float* ln_b  = (const float*)d_in[2];
    const float* inpw  = (const float*)d_in[3];
    const float* convw = (const float*)d_in[4];
    const float* convb = (const float*)d_in[5];
    const float* xprw  = (const float*)d_in[6];
    const float* dtw   = (const float*)d_in[7];
    const float* dtb   = (const float*)d_in[8];
    const float* Alog  = (const float*)d_in[9];
    const float* Ablog = (const float*)d_in[10];
    const float* Dmat  = (const float*)d_in[11];
    const float* outw  = (const float*)d_in[12];
    const float* mn_w  = (const float*)d_in[13];
    const float* mn_b  = (const float*)d_in[14];
    const int*   rl    = (const int*)  d_in[15];

    dim3 tposeGrid(LL / 32, CC / 32, GG);
    dim3 tposeBlk(32, 8);

    wprep<<<(NIN + NXP + NOUT + 255) / 256, 256>>>(inpw, xprw, outw);
    mean_kernel<<<tposeGrid, tposeBlk>>>(data, rl);
    ln_fused<0, 1><<<NROWS / 8, 256>>>(nullptr, nullptr, ln_w, ln_b);

    for (int i = 0; i < DEPTHN; i++) {
        const float* cw_i   = convw + i * CC * 4;
        const float* cb_i   = convb + i * CC;
        const float* dtw_i  = dtw   + (size_t)i * CC * RNK;
        const float* dtb_i  = dtb   + i * CC;
        const float* Al_i   = Alog  + (size_t)i * CC * NST;
        const float* Ab_i   = Ablog + (size_t)i * CC * NST;
        const float* D_i    = Dmat  + i * CC;
        const float* mnw_i  = mn_w  + i * CC;
        const float* mnb_i  = mn_b  + i * CC;

        tc_gemm<0, 128><<<dim3(512 / 128, NROWS / 128), 256>>>(i);
        conv_silu_kernel<<<(2 * NROWS * CC) / (256 * 4), 256>>>(cw_i, cb_i);
        tc_gemm<1, 32><<<dim3(1, NROWS / 128, 2), 256>>>(i);
        dtproj_kernel<<<dim3(NROWS / 64, 2), 256>>>(dtw_i, dtb_i);
        scan_phase1<<<dim3(NCH, GG, 2), 256>>>(Al_i, Ab_i);
        scan_phase2<<<(2 * GG * CC * NST) / 256, 256>>>(Al_i, Ab_i);
        scan_phase3<<<dim3(NCH, GG, 2), 256>>>(Al_i, Ab_i, D_i);
        tc_gemm<2, 128><<<dim3(256 / 128, NROWS / 128), 256>>>(i);
        if (i < DEPTHN - 1)
            ln_fused<1, 1><<<NROWS / 8, 256>>>(mnw_i, mnb_i,
                                               ln_w + (i + 1) * CC, ln_b + (i + 1) * CC);
        else
            ln_fused<1, 0><<<NROWS / 8, 256>>>(mnw_i, mnb_i, nullptr, nullptr);
    }

    out_transpose<<<tposeGrid, tposeBlk>>>((float*)d_out);
}